// round 10
// baseline (speedup 1.0000x reference)
#include <cuda_runtime.h>
#include <cuda_bf16.h>
#include <cstdint>

// Problem constants: B=16 graphs, N=4096 nodes/graph, 64 features, k=10.
#define KNN_K      10
#define BGRAPHS    16
#define FEATS      64
#define MAX_TOTAL  65536
#define NODES      4096
#define NPAIR      (NODES / 2)
#define QPB        256            // queries per block
#define TPB        512            // 2 threads (directions) per query
#define NBUCKET    1024
#define BUCKET_W   (8.0f / NBUCKET)
#define EXIT_MARGIN 1e-4f         // covers f32 cancellation in computed d2

// Scratch (device globals: no allocation allowed in kernel_launch)
__device__ float  g_sum[MAX_TOTAL * FEATS];    // 16 MB accumulators
__device__ int    g_cnt[MAX_TOTAL];            // reverse-degree counts
__device__ int    g_nbr[MAX_TOTAL * KNN_K];    // knn neighbor lists (global idx)
__device__ float4 g_spos[MAX_TOTAL];           // x-sorted positions {x,y,z,|p|^2}
__device__ int    g_sidx[MAX_TOTAL];           // sorted-rank -> original local idx

// ---------- packed f32x2 helpers (sm_103a) ----------
__device__ __forceinline__ uint64_t pack2(float a, float b) {
    uint64_t r; asm("mov.b64 %0, {%1, %2};" : "=l"(r) : "f"(a), "f"(b)); return r;
}
__device__ __forceinline__ void unpack2(float& lo, float& hi, uint64_t v) {
    asm("mov.b64 {%0, %1}, %2;" : "=f"(lo), "=f"(hi) : "l"(v));
}
__device__ __forceinline__ uint64_t mul2(uint64_t a, uint64_t b) {
    uint64_t r; asm("mul.rn.f32x2 %0, %1, %2;" : "=l"(r) : "l"(a), "l"(b)); return r;
}
__device__ __forceinline__ uint64_t add2(uint64_t a, uint64_t b) {
    uint64_t r; asm("add.rn.f32x2 %0, %1, %2;" : "=l"(r) : "l"(a), "l"(b)); return r;
}
__device__ __forceinline__ uint64_t fma2(uint64_t a, uint64_t b, uint64_t c) {
    uint64_t r; asm("fma.rn.f32x2 %0, %1, %2, %3;" : "=l"(r) : "l"(a), "l"(b), "l"(c)); return r;
}

// sorted-ascending ripple insert of one u64 key (d2_bits<<32 | orig_idx):
// exact (distance, then original-index) order == jax.lax.top_k tie semantics.
#define INS(cin) do {                                                     \
    uint64_t c_ = (cin);                                                  \
    _Pragma("unroll")                                                     \
    for (int t_ = 0; t_ < KNN_K; ++t_) {                                  \
        uint64_t mn_ = (c_ < kd[t_]) ? c_ : kd[t_];                       \
        uint64_t mx_ = (c_ < kd[t_]) ? kd[t_] : c_;                       \
        kd[t_] = mn_; c_ = mx_;                                           \
    }                                                                     \
    thr = __uint_as_float((unsigned)(kd[KNN_K - 1] >> 32));               \
} while (0)

// distance + conditional insert for one pair; exports x0_,x1_.
#define PAIR_BODY(jp, x0_, x1_) \
    ulonglong2 xy = pxy[jp];                                              \
    ulonglong2 zw = pzw[jp];                                              \
    uint64_t dot = mul2(qx2, xy.x);                                       \
    dot = fma2(qy2, xy.y, dot);                                           \
    dot = fma2(qz2, zw.x, dot);                                           \
    uint64_t s2  = add2(qsq2, zw.y);                                      \
    uint64_t d2p = fma2(m2, dot, s2);                                     \
    float lo, hi; unpack2(lo, hi, d2p);                                   \
    float x0_, x1_; unpack2(x0_, x1_, xy.x);                              \
    if (fminf(lo, hi) < thr) {                                            \
        int j0_ = (jp) * 2;                                               \
        if (lo < thr && j0_ != qr) {                                      \
            uint64_t key = ((uint64_t)__float_as_uint(lo) << 32)          \
                         | (unsigned)ssid[j0_];                           \
            INS(key);                                                     \
        }                                                                 \
        if (hi < thr && (j0_ + 1) != qr) {                                \
            uint64_t key = ((uint64_t)__float_as_uint(hi) << 32)          \
                         | (unsigned)ssid[j0_ + 1];                       \
            INS(key);                                                     \
        }                                                                 \
    }

__device__ __forceinline__ int xbucket(float x) {
    int bk = (int)floorf((x + 4.0f) * (NBUCKET / 8.0f));
    return max(0, min(NBUCKET - 1, bk));
}

// ---------------------------------------------------------------------------
// K0: counting-sort each graph's points into 1024 x-buckets (within-bucket
// order atomic-arbitrary; exactness preserved: selection is a total order on
// (d2, orig_idx)). w = |p|^2 with exact reference rounding (no contraction).
// ---------------------------------------------------------------------------
__global__ void sort_kernel(const float* __restrict__ pos) {
    __shared__ int cnt[NBUCKET];
    __shared__ int tsum[256];
    __shared__ int off[NBUCKET];

    const int b   = blockIdx.x;
    const int tid = threadIdx.x;        // 256 threads
    const float* pg = pos + (size_t)b * NODES * 3;

#pragma unroll
    for (int i = 0; i < NBUCKET / 256; ++i) cnt[tid + i * 256] = 0;
    __syncthreads();

    for (int j = tid; j < NODES; j += 256)
        atomicAdd(&cnt[xbucket(pg[3 * j])], 1);
    __syncthreads();

    {
        int c0 = cnt[4 * tid], c1 = cnt[4 * tid + 1];
        int c2 = cnt[4 * tid + 2], c3 = cnt[4 * tid + 3];
        tsum[tid] = c0 + c1 + c2 + c3;
        __syncthreads();
        for (int d = 1; d < 256; d <<= 1) {
            int v = (tid >= d) ? tsum[tid - d] : 0;
            __syncthreads();
            tsum[tid] += v;
            __syncthreads();
        }
        int base = tsum[tid] - (c0 + c1 + c2 + c3);
        off[4 * tid]     = base;
        off[4 * tid + 1] = base + c0;
        off[4 * tid + 2] = base + c0 + c1;
        off[4 * tid + 3] = base + c0 + c1 + c2;
    }
    __syncthreads();

    for (int j = tid; j < NODES; j += 256) {
        float x = pg[3 * j], y = pg[3 * j + 1], z = pg[3 * j + 2];
        float w = __fadd_rn(__fadd_rn(__fmul_rn(x, x), __fmul_rn(y, y)),
                            __fmul_rn(z, z));        // == jnp.sum(pos*pos)
        int p = atomicAdd(&off[xbucket(x)], 1);
        g_spos[b * NODES + p] = make_float4(x, y, z, w);
        g_sidx[b * NODES + p] = j;
    }
}

// ---------------------------------------------------------------------------
// K1: x-sorted kNN, 2 threads/query split by SCAN DIRECTION.
//   Warp pair (2w, 2w+1) shares query group w (32 queries, lane-grouped by
//   transverse radius). h = warp&1: h=1 scans pairs [S, NPAIR) ascending,
//   h=0 scans [0, S) descending, S = tile-center pair (8-aligned).
//   Each side keeps its own top-10 (u64 (d2,idx) keys) and exits when for
//   ALL lanes max(|x_last - qx| - BUCKET_W, 0)^2 >= thr + EXIT_MARGIN
//   (bucket-monotone order => bound permanent => side scan exact).
//   Union of side top-10s contains the global top-10 (sides partition the
//   rank space); merged exactly via sorted-list bitonic min.
// d2 bit-identical to reference ((qsq+w) - 2*dot; 2*dot exact).
// ---------------------------------------------------------------------------
__global__ void __launch_bounds__(TPB) knn_kernel(int dummy) {
    extern __shared__ float4 sm[];
    float4*   sxy  = sm;                    // NPAIR {x0,x1,y0,y1}
    float4*   szw  = sm + NPAIR;            // NPAIR {z0,z1,w0,w1}
    int*      ssid = (int*)(sm + NODES);    // NODES rank -> orig idx
    uint64_t* mbuf = (uint64_t*)sm;         // merge buffer (overlays sxy later)
    __shared__ uint64_t skey[QPB];          // (t_bits<<32)|rank lane grouping

    const int tilesPerGraph = NODES / QPB;  // 16
    const int b    = blockIdx.x / tilesPerGraph;
    const int tile = blockIdx.x % tilesPerGraph;
    const int tid  = threadIdx.x;
    const int gbase = b * NODES;

    // ---- fused zeroing of accumulators + counts (block-flat region) ----
    {
        float4 z = make_float4(0.f, 0.f, 0.f, 0.f);
        int nb = blockIdx.x * QPB;
        float4* dst = reinterpret_cast<float4*>(g_sum) + (size_t)nb * (FEATS / 4);
#pragma unroll
        for (int i = 0; i < (QPB * FEATS / 4) / TPB; ++i) dst[i * TPB + tid] = z;
        if (tid < QPB) g_cnt[nb + tid] = 0;
    }

    // ---- stage sorted positions (pair-transposed) + rank->orig idx ----
    for (int jp = tid; jp < NPAIR; jp += TPB) {
        float4 a = g_spos[gbase + 2 * jp];
        float4 c = g_spos[gbase + 2 * jp + 1];
        sxy[jp] = make_float4(a.x, c.x, a.y, c.y);
        szw[jp] = make_float4(a.z, c.z, a.w, c.w);
    }
    for (int j = tid; j < NODES; j += TPB)
        ssid[j] = g_sidx[gbase + j];
    __syncthreads();

    // ---- lane grouping: bitonic sort tile queries by transverse radius ----
    if (tid < QPB) {
        int   qr0 = tile * QPB + tid;
        float4 xy0 = sxy[qr0 >> 1];
        float4 zw0 = szw[qr0 >> 1];
        float xq = (qr0 & 1) ? xy0.y : xy0.x;
        float wq = (qr0 & 1) ? zw0.w : zw0.z;
        float t  = fmaxf(wq - xq * xq, 0.0f);
        skey[tid] = ((uint64_t)__float_as_uint(t) << 32) | (unsigned)qr0;
    }
    __syncthreads();
    for (int k = 2; k <= QPB; k <<= 1) {
        for (int j = k >> 1; j > 0; j >>= 1) {
            if (tid < QPB) {
                int ixj = tid ^ j;
                if (ixj > tid) {
                    uint64_t a = skey[tid], c = skey[ixj];
                    bool asc = ((tid & k) == 0);
                    if ((a > c) == asc) { skey[tid] = c; skey[ixj] = a; }
                }
            }
            __syncthreads();
        }
    }

    // ---- thread -> (query, direction) ----
    const int w  = tid >> 5;             // warp 0..15
    const int l  = tid & 31;
    const int h  = w & 1;                // 0 = down, 1 = up
    const int q  = (w >> 1) * 32 + l;    // query slot 0..255
    const int qr = (int)(unsigned)(skey[q] & 0xffffffffu);

    float qx, qy, qz, qsq;
    {
        float4 xy = sxy[qr >> 1];
        float4 zw = szw[qr >> 1];
        if (qr & 1) { qx = xy.y; qy = xy.w; qz = zw.y; qsq = zw.w; }
        else        { qx = xy.x; qy = xy.z; qz = zw.x; qsq = zw.z; }
    }
    const uint64_t qx2  = pack2(qx, qx);
    const uint64_t qy2  = pack2(qy, qy);
    const uint64_t qz2  = pack2(qz, qz);
    const uint64_t qsq2 = pack2(qsq, qsq);
    const uint64_t m2   = pack2(-2.0f, -2.0f);

    uint64_t kd[KNN_K];
#pragma unroll
    for (int t = 0; t < KNN_K; ++t) kd[t] = 0x7f800000ffffffffULL;
    float thr = __int_as_float(0x7f800000);

    const ulonglong2* pxy = reinterpret_cast<const ulonglong2*>(sxy);
    const ulonglong2* pzw = reinterpret_cast<const ulonglong2*>(szw);

    // split point: tile-center pair (multiple of 8; NPAIR - S also mult of 8)
    const int S = tile * (QPB >> 1) + (QPB >> 2);

    if (h == 1) {
        // ---- upward side: pairs [S, NPAIR), 8-pair chunks ----
        for (int jc = S; jc < NPAIR; jc += 8) {
            float lastx = 0.0f;
#pragma unroll
            for (int i = 0; i < 8; ++i) {
                int jp = jc + i;
                PAIR_BODY(jp, ux0, ux1);
                (void)ux0;
                lastx = ux1;               // highest rank processed
            }
            float g = fmaxf(lastx - qx - BUCKET_W, 0.0f);
            if (__all_sync(0xffffffffu, g * g >= thr + EXIT_MARGIN)) break;
        }
    } else {
        // ---- downward side: pairs [0, S) descending, 8-pair chunks ----
        for (int jc = S - 8; jc >= 0; jc -= 8) {
            float lastx = 0.0f;
#pragma unroll
            for (int i = 7; i >= 0; --i) {
                int jp = jc + i;
                PAIR_BODY(jp, dx0, dx1);
                (void)dx1;
                lastx = dx0;               // lowest rank processed
            }
            float g = fmaxf(qx - lastx - BUCKET_W, 0.0f);
            if (__all_sync(0xffffffffu, g * g >= thr + EXIT_MARGIN)) break;
        }
    }

    // ---- exact merge of the two sides (disjoint rank ranges) ----
    const int my_oid = gbase + ssid[qr];   // ssid region is not overlaid
    __syncthreads();                        // all scans done; sxy reusable
    if (h == 1) {
#pragma unroll
        for (int t = 0; t < KNN_K; ++t) mbuf[q * KNN_K + t] = kd[t];
    }
    __syncthreads();
    if (h == 0) {
#pragma unroll
        for (int t = 0; t < KNN_K; ++t) {
            uint64_t r = mbuf[q * KNN_K + (KNN_K - 1 - t)];
            kd[t] = (kd[t] < r) ? kd[t] : r;   // 10 smallest of union (set)
        }
#pragma unroll
        for (int t = 0; t < KNN_K; ++t)
            g_nbr[my_oid * KNN_K + t] = gbase + (int)(unsigned)kd[t];
    }
}

// ---------------------------------------------------------------------------
// K2: scatter x[query] into g_sum[neighbor] with vectorized L2 reductions,
// plus reverse-degree counting (lane c==0 of each 16-lane query group).
// ---------------------------------------------------------------------------
__global__ void scatter_kernel(const float* __restrict__ x, int total) {
    int t = blockIdx.x * blockDim.x + threadIdx.x;
    int q = t >> 4;
    int c = t & 15;
    if (q >= total) return;

    float4 v = reinterpret_cast<const float4*>(x)[q * (FEATS / 4) + c];
    const int* nb = &g_nbr[q * KNN_K];

#pragma unroll
    for (int n = 0; n < KNN_K; ++n) {
        int j = nb[n];
        float* p = g_sum + (size_t)j * FEATS + c * 4;
        asm volatile("red.global.add.v4.f32 [%0], {%1, %2, %3, %4};"
                     :: "l"(p), "f"(v.x), "f"(v.y), "f"(v.z), "f"(v.w)
                     : "memory");
        if (c == 0)
            asm volatile("red.global.add.u32 [%0], %1;"
                         :: "l"(&g_cnt[j]), "r"(1) : "memory");
    }
}

// ---------------------------------------------------------------------------
// K3: out[r] = sum_d | x[r,d] - sum[r,d] / max(cnt[r],1) |   (warp per node)
// ---------------------------------------------------------------------------
__global__ void out_kernel(const float* __restrict__ x, float* __restrict__ out,
                           int total) {
    int node = (blockIdx.x * blockDim.x + threadIdx.x) >> 5;
    int lane = threadIdx.x & 31;
    if (node >= total) return;

    float c   = (float)g_cnt[node];
    float inv = 1.0f / fmaxf(c, 1.0f);

    const float* xr = x + (size_t)node * FEATS;
    const float* sr = g_sum + (size_t)node * FEATS;

    float acc = fabsf(xr[lane]      - sr[lane]      * inv)
              + fabsf(xr[lane + 32] - sr[lane + 32] * inv);
#pragma unroll
    for (int o = 16; o > 0; o >>= 1) acc += __shfl_xor_sync(0xffffffffu, acc, o);
    if (lane == 0) out[node] = acc;
}

// ---------------------------------------------------------------------------
extern "C" void kernel_launch(void* const* d_in, const int* in_sizes, int n_in,
                              void* d_out, int out_size) {
    const float* x   = (const float*)d_in[0];   // [total, 64] fp32
    const float* pos = (const float*)d_in[1];   // [total, 3]  fp32

    const int total = in_sizes[0] / FEATS;      // 65536
    float* out = (float*)d_out;

    // K0: per-graph counting sort by x (1024 buckets)
    sort_kernel<<<BGRAPHS, 256>>>(pos);

    // K1: kNN, direction-split 2 threads/query
    size_t smem = (size_t)NODES * sizeof(float4) + NODES * sizeof(int);
    cudaFuncSetAttribute(knn_kernel, cudaFuncAttributeMaxDynamicSharedMemorySize,
                         (int)smem);
    knn_kernel<<<total / QPB, TPB, smem>>>(0);

    // K2: vectorized atomic scatter + counts (16 lanes per query)
    int threads2 = total * 16;
    scatter_kernel<<<(threads2 + 127) / 128, 128>>>(x, total);

    // K3: finalize L1 norm (warp per node)
    out_kernel<<<(total * 32 + 255) / 256, 256>>>(x, out, total);
}

// round 11
// speedup vs baseline: 1.1284x; 1.1284x over previous
#include <cuda_runtime.h>
#include <cuda_bf16.h>
#include <cstdint>

// Problem constants: B=16 graphs, N=4096 nodes/graph, 64 features, k=10.
#define KNN_K      10
#define BGRAPHS    16
#define FEATS      64
#define MAX_TOTAL  65536
#define NODES      4096
#define NPAIR      (NODES / 2)
#define QPB        256
#define NBUCKET    1024
#define BUCKET_W   (8.0f / NBUCKET)   // x-bucket width (range [-4,4])
#define EXIT_MARGIN 1e-3f             // covers f32 cancellation in computed d2

// Scratch (device globals: no allocation allowed in kernel_launch)
__device__ float  g_sum[MAX_TOTAL * FEATS];    // 16 MB accumulators
__device__ int    g_cnt[MAX_TOTAL];            // reverse-degree counts
__device__ int    g_nbr[MAX_TOTAL * KNN_K];    // knn neighbor lists (global idx)
__device__ float4 g_spos[MAX_TOTAL];           // x-sorted positions {x,y,z,|p|^2}
__device__ int    g_sidx[MAX_TOTAL];           // sorted-rank -> original local idx

// ---------- packed f32x2 helpers (sm_103a) ----------
__device__ __forceinline__ uint64_t pack2(float a, float b) {
    uint64_t r; asm("mov.b64 %0, {%1, %2};" : "=l"(r) : "f"(a), "f"(b)); return r;
}
__device__ __forceinline__ void unpack2(float& lo, float& hi, uint64_t v) {
    asm("mov.b64 {%0, %1}, %2;" : "=f"(lo), "=f"(hi) : "l"(v));
}
__device__ __forceinline__ uint64_t mul2(uint64_t a, uint64_t b) {
    uint64_t r; asm("mul.rn.f32x2 %0, %1, %2;" : "=l"(r) : "l"(a), "l"(b)); return r;
}
__device__ __forceinline__ uint64_t add2(uint64_t a, uint64_t b) {
    uint64_t r; asm("add.rn.f32x2 %0, %1, %2;" : "=l"(r) : "l"(a), "l"(b)); return r;
}
__device__ __forceinline__ uint64_t fma2(uint64_t a, uint64_t b, uint64_t c) {
    uint64_t r; asm("fma.rn.f32x2 %0, %1, %2, %3;" : "=l"(r) : "l"(a), "l"(b), "l"(c)); return r;
}

// sorted-ascending ripple insert of one u64 key (d2_bits<<32 | orig_idx):
// exact (distance, then original-index) order == jax.lax.top_k tie semantics.
#define INS(cin) do {                                                     \
    uint64_t c_ = (cin);                                                  \
    _Pragma("unroll")                                                     \
    for (int t_ = 0; t_ < KNN_K; ++t_) {                                  \
        uint64_t mn_ = (c_ < kd[t_]) ? c_ : kd[t_];                       \
        uint64_t mx_ = (c_ < kd[t_]) ? kd[t_] : c_;                       \
        kd[t_] = mn_; c_ = mx_;                                           \
    }                                                                     \
    thr = __uint_as_float((unsigned)(kd[KNN_K - 1] >> 32));               \
} while (0)

// distance + conditional insert for one pair; exports x0_,x1_.
#define PAIR_BODY(jp, x0_, x1_) \
    ulonglong2 xy = pxy[jp];                                              \
    ulonglong2 zw = pzw[jp];                                              \
    uint64_t dot = mul2(qx2, xy.x);                                       \
    dot = fma2(qy2, xy.y, dot);                                           \
    dot = fma2(qz2, zw.x, dot);                                           \
    uint64_t s2  = add2(qsq2, zw.y);                                      \
    uint64_t d2p = fma2(m2, dot, s2);                                     \
    float lo, hi; unpack2(lo, hi, d2p);                                   \
    float x0_, x1_; unpack2(x0_, x1_, xy.x);                              \
    if (fminf(lo, hi) < thr) {                                            \
        int j0_ = (jp) * 2;                                               \
        if (lo < thr && j0_ != qr) {                                      \
            uint64_t key = ((uint64_t)__float_as_uint(lo) << 32)          \
                         | (unsigned)ssid[j0_];                           \
            INS(key);                                                     \
        }                                                                 \
        if (hi < thr && (j0_ + 1) != qr) {                                \
            uint64_t key = ((uint64_t)__float_as_uint(hi) << 32)          \
                         | (unsigned)ssid[j0_ + 1];                       \
            INS(key);                                                     \
        }                                                                 \
    }

__device__ __forceinline__ int xbucket(float x) {
    int bk = (int)floorf((x + 4.0f) * (NBUCKET / 8.0f));
    return max(0, min(NBUCKET - 1, bk));
}

// ---------------------------------------------------------------------------
// K0: counting-sort each graph's points into 1024 x-buckets (within-bucket
// order atomic-arbitrary; exactness preserved: selection is a total order on
// (d2, orig_idx)). w = |p|^2 with exact reference rounding (no contraction).
// ---------------------------------------------------------------------------
__global__ void sort_kernel(const float* __restrict__ pos) {
    __shared__ int cnt[NBUCKET];
    __shared__ int tsum[256];
    __shared__ int off[NBUCKET];

    const int b   = blockIdx.x;
    const int tid = threadIdx.x;        // 256 threads
    const float* pg = pos + (size_t)b * NODES * 3;

#pragma unroll
    for (int i = 0; i < NBUCKET / 256; ++i) cnt[tid + i * 256] = 0;
    __syncthreads();

    for (int j = tid; j < NODES; j += 256)
        atomicAdd(&cnt[xbucket(pg[3 * j])], 1);
    __syncthreads();

    // two-level exclusive prefix: thread t owns bins [4t, 4t+4)
    {
        int c0 = cnt[4 * tid], c1 = cnt[4 * tid + 1];
        int c2 = cnt[4 * tid + 2], c3 = cnt[4 * tid + 3];
        tsum[tid] = c0 + c1 + c2 + c3;
        __syncthreads();
        for (int d = 1; d < 256; d <<= 1) {
            int v = (tid >= d) ? tsum[tid - d] : 0;
            __syncthreads();
            tsum[tid] += v;
            __syncthreads();
        }
        int base = tsum[tid] - (c0 + c1 + c2 + c3);
        off[4 * tid]     = base;
        off[4 * tid + 1] = base + c0;
        off[4 * tid + 2] = base + c0 + c1;
        off[4 * tid + 3] = base + c0 + c1 + c2;
    }
    __syncthreads();

    for (int j = tid; j < NODES; j += 256) {
        float x = pg[3 * j], y = pg[3 * j + 1], z = pg[3 * j + 2];
        float w = __fadd_rn(__fadd_rn(__fmul_rn(x, x), __fmul_rn(y, y)),
                            __fmul_rn(z, z));        // == jnp.sum(pos*pos)
        int p = atomicAdd(&off[xbucket(x)], 1);
        g_spos[b * NODES + p] = make_float4(x, y, z, w);
        g_sidx[b * NODES + p] = j;
    }
}

// ---------------------------------------------------------------------------
// K1: x-sorted kNN (R8 structure), center-out CORE ordering, exact early exit,
// transverse-radius lane grouping.
//   core: pair range [clo_p, chi_p) (= tile +-80 ranks), executed as two
//         fixed-bound linear loops: ascending from the tile-center pair, then
//         descending from it -> candidates arrive ~distance-increasing for
//         each query's near half, collapsing transient inserts.
//   expansion: per-direction 8-pair chunks with bucket-safe exit votes.
// Exit proof (bucket-monotone order): future ranks above have
//   x >= x(highest processed rank) - BUCKET_W; below symmetric. If for all
// lanes max(gap,0)^2 >= thr + EXIT_MARGIN, stop (margin >> computed-d2 error).
// thr = +inf until a lane holds 10 -> no premature exit. All bounds are
// multiples of 8 -> unconditional inner loops.
// d2 bit-identical to reference ((qsq+w) - 2*dot; 2*dot exact).
// ---------------------------------------------------------------------------
__global__ void __launch_bounds__(QPB) knn_kernel(int dummy) {
    extern __shared__ float4 sm[];
    float4* sxy  = sm;                    // NPAIR {x0,x1,y0,y1}
    float4* szw  = sm + NPAIR;            // NPAIR {z0,z1,w0,w1}
    int*    ssid = (int*)(sm + NODES);    // NODES rank -> orig idx
    __shared__ uint64_t skey[QPB];        // (t_bits<<32)|rank for lane grouping

    const int tilesPerGraph = NODES / QPB;  // 16
    const int b    = blockIdx.x / tilesPerGraph;
    const int tile = blockIdx.x % tilesPerGraph;
    const int tid  = threadIdx.x;
    const int gbase = b * NODES;

    // ---- fused zeroing of accumulators + counts (block-flat region) ----
    {
        float4 z = make_float4(0.f, 0.f, 0.f, 0.f);
        int nb = blockIdx.x * QPB;
        float4* dst = reinterpret_cast<float4*>(g_sum) + (size_t)nb * (FEATS / 4);
#pragma unroll
        for (int i = 0; i < 16; ++i) dst[i * QPB + tid] = z;
        g_cnt[nb + tid] = 0;
    }

    // ---- stage sorted positions (pair-transposed) + rank->orig idx ----
    for (int jp = tid; jp < NPAIR; jp += QPB) {
        float4 a = g_spos[gbase + 2 * jp];
        float4 c = g_spos[gbase + 2 * jp + 1];
        sxy[jp] = make_float4(a.x, c.x, a.y, c.y);
        szw[jp] = make_float4(a.z, c.z, a.w, c.w);
    }
    for (int j = tid; j < NODES; j += QPB)
        ssid[j] = g_sidx[gbase + j];
    __syncthreads();

    // ---- lane grouping: bitonic sort tile queries by transverse radius ----
    {
        int   qr0 = tile * QPB + tid;
        float4 xy0 = sxy[qr0 >> 1];
        float4 zw0 = szw[qr0 >> 1];
        float xq = (qr0 & 1) ? xy0.y : xy0.x;
        float wq = (qr0 & 1) ? zw0.w : zw0.z;
        float t  = fmaxf(wq - xq * xq, 0.0f);
        skey[tid] = ((uint64_t)__float_as_uint(t) << 32) | (unsigned)qr0;
    }
    __syncthreads();
    for (int k = 2; k <= QPB; k <<= 1) {
        for (int j = k >> 1; j > 0; j >>= 1) {
            int ixj = tid ^ j;
            if (ixj > tid) {
                uint64_t a = skey[tid], c = skey[ixj];
                bool asc = ((tid & k) == 0);
                if ((a > c) == asc) { skey[tid] = c; skey[ixj] = a; }
            }
            __syncthreads();
        }
    }

    // ---- own query: permuted rank ----
    const int qr = (int)(unsigned)(skey[tid] & 0xffffffffu);
    float qx, qy, qz, qsq;
    {
        float4 xy = sxy[qr >> 1];
        float4 zw = szw[qr >> 1];
        if (qr & 1) { qx = xy.y; qy = xy.w; qz = zw.y; qsq = zw.w; }
        else        { qx = xy.x; qy = xy.z; qz = zw.x; qsq = zw.z; }
    }
    const uint64_t qx2  = pack2(qx, qx);
    const uint64_t qy2  = pack2(qy, qy);
    const uint64_t qz2  = pack2(qz, qz);
    const uint64_t qsq2 = pack2(qsq, qsq);
    const uint64_t m2   = pack2(-2.0f, -2.0f);

    uint64_t kd[KNN_K];
#pragma unroll
    for (int t = 0; t < KNN_K; ++t) kd[t] = 0x7f800000ffffffffULL;
    float thr = __int_as_float(0x7f800000);

    const ulonglong2* pxy = reinterpret_cast<const ulonglong2*>(sxy);
    const ulonglong2* pzw = reinterpret_cast<const ulonglong2*>(szw);

    // core pair bounds (all multiples of 8): [clo_p, chi_p), mid = tile center
    const int tb    = tile * QPB;
    const int clo_p = max(0, tb - 80) >> 1;
    const int chi_p = min(NODES, tb + QPB + 80) >> 1;
    const int mid_p = (tb >> 1) + (QPB >> 2);     // tile-center pair

    // ---- core, ascending half: [mid_p, chi_p) ----
#pragma unroll 4
    for (int jp = mid_p; jp < chi_p; ++jp) {
        PAIR_BODY(jp, ax0, ax1);
        (void)ax0; (void)ax1;
    }
    // ---- core, descending half: (mid_p-1 .. clo_p] ----
#pragma unroll 4
    for (int jp = mid_p - 1; jp >= clo_p; --jp) {
        PAIR_BODY(jp, bx0, bx1);
        (void)bx0; (void)bx1;
    }

    // ---- upward expansion: 8-pair chunks, extremal-rank exact exit ----
    for (int jc = chi_p; jc < NPAIR; jc += 8) {
        float lastx = 0.0f;
#pragma unroll
        for (int i = 0; i < 8; ++i) {
            int jp = jc + i;
            PAIR_BODY(jp, ux0, ux1);
            (void)ux0;
            lastx = ux1;                   // x of highest processed rank
        }
        float g = fmaxf(lastx - qx - BUCKET_W, 0.0f);
        if (__all_sync(0xffffffffu, g * g >= thr + EXIT_MARGIN)) break;
    }

    // ---- downward expansion: 8-pair chunks, extremal-rank exact exit ----
    for (int jc = clo_p - 8; jc >= 0; jc -= 8) {
        float lastx = 0.0f;
#pragma unroll
        for (int i = 7; i >= 0; --i) {
            int jp = jc + i;
            PAIR_BODY(jp, dx0, dx1);
            (void)dx1;
            lastx = dx0;                   // x of lowest processed rank
        }
        float g = fmaxf(qx - lastx - BUCKET_W, 0.0f);
        if (__all_sync(0xffffffffu, g * g >= thr + EXIT_MARGIN)) break;
    }

    // ---- write neighbor list for this query's ORIGINAL node id ----
    const int my_oid = gbase + ssid[qr];
#pragma unroll
    for (int t = 0; t < KNN_K; ++t)
        g_nbr[my_oid * KNN_K + t] = gbase + (int)(unsigned)kd[t];
}

// ---------------------------------------------------------------------------
// K2: scatter x[query] into g_sum[neighbor] with vectorized L2 reductions,
// plus reverse-degree counting (lane c==0 of each 16-lane query group).
// ---------------------------------------------------------------------------
__global__ void scatter_kernel(const float* __restrict__ x, int total) {
    int t = blockIdx.x * blockDim.x + threadIdx.x;
    int q = t >> 4;
    int c = t & 15;
    if (q >= total) return;

    float4 v = reinterpret_cast<const float4*>(x)[q * (FEATS / 4) + c];
    const int* nb = &g_nbr[q * KNN_K];

#pragma unroll
    for (int n = 0; n < KNN_K; ++n) {
        int j = nb[n];
        float* p = g_sum + (size_t)j * FEATS + c * 4;
        asm volatile("red.global.add.v4.f32 [%0], {%1, %2, %3, %4};"
                     :: "l"(p), "f"(v.x), "f"(v.y), "f"(v.z), "f"(v.w)
                     : "memory");
        if (c == 0)
            asm volatile("red.global.add.u32 [%0], %1;"
                         :: "l"(&g_cnt[j]), "r"(1) : "memory");
    }
}

// ---------------------------------------------------------------------------
// K3: out[r] = sum_d | x[r,d] - sum[r,d] / max(cnt[r],1) |   (warp per node)
// ---------------------------------------------------------------------------
__global__ void out_kernel(const float* __restrict__ x, float* __restrict__ out,
                           int total) {
    int node = (blockIdx.x * blockDim.x + threadIdx.x) >> 5;
    int lane = threadIdx.x & 31;
    if (node >= total) return;

    float c   = (float)g_cnt[node];
    float inv = 1.0f / fmaxf(c, 1.0f);

    const float* xr = x + (size_t)node * FEATS;
    const float* sr = g_sum + (size_t)node * FEATS;

    float acc = fabsf(xr[lane]      - sr[lane]      * inv)
              + fabsf(xr[lane + 32] - sr[lane + 32] * inv);
#pragma unroll
    for (int o = 16; o > 0; o >>= 1) acc += __shfl_xor_sync(0xffffffffu, acc, o);
    if (lane == 0) out[node] = acc;
}

// ---------------------------------------------------------------------------
extern "C" void kernel_launch(void* const* d_in, const int* in_sizes, int n_in,
                              void* d_out, int out_size) {
    const float* x   = (const float*)d_in[0];   // [total, 64] fp32
    const float* pos = (const float*)d_in[1];   // [total, 3]  fp32

    const int total = in_sizes[0] / FEATS;      // 65536
    float* out = (float*)d_out;

    // K0: per-graph counting sort by x (1024 buckets)
    sort_kernel<<<BGRAPHS, 256>>>(pos);

    // K1: kNN (smem: 64KB pos + 16KB idx dynamic, +2KB static skey)
    size_t smem = (size_t)NODES * sizeof(float4) + NODES * sizeof(int);
    cudaFuncSetAttribute(knn_kernel, cudaFuncAttributeMaxDynamicSharedMemorySize,
                         (int)smem);
    knn_kernel<<<total / QPB, QPB, smem>>>(0);

    // K2: vectorized atomic scatter + counts (16 lanes per query)
    int threads2 = total * 16;
    scatter_kernel<<<(threads2 + 127) / 128, 128>>>(x, total);

    // K3: finalize L1 norm (warp per node)
    out_kernel<<<(total * 32 + 255) / 256, 256>>>(x, out, total);
}

// round 12
// speedup vs baseline: 1.3597x; 1.2050x over previous
#include <cuda_runtime.h>
#include <cuda_bf16.h>
#include <cstdint>

// Problem constants: B=16 graphs, N=4096 nodes/graph, 64 features, k=10.
#define KNN_K      10
#define BGRAPHS    16
#define FEATS      64
#define MAX_TOTAL  65536
#define NODES      4096
#define NPAIR      (NODES / 2)
#define QPB        256            // queries per block
#define TPB        512            // 2 threads (pair-parity halves) per query
#define NBUCKET    1024
#define BUCKET_W   (8.0f / NBUCKET)
#define EXIT_MARGIN 1e-4f         // covers f32 cancellation in computed d2

// Scratch (device globals: no allocation allowed in kernel_launch)
__device__ float  g_sum[MAX_TOTAL * FEATS];    // 16 MB accumulators
__device__ int    g_cnt[MAX_TOTAL];            // reverse-degree counts
__device__ int    g_nbr[MAX_TOTAL * KNN_K];    // knn neighbor lists (global idx)
__device__ float4 g_spos[MAX_TOTAL];           // x-sorted positions {x,y,z,|p|^2}
__device__ int    g_sidx[MAX_TOTAL];           // sorted-rank -> original local idx

// ---------- packed f32x2 helpers (sm_103a) ----------
__device__ __forceinline__ uint64_t pack2(float a, float b) {
    uint64_t r; asm("mov.b64 %0, {%1, %2};" : "=l"(r) : "f"(a), "f"(b)); return r;
}
__device__ __forceinline__ void unpack2(float& lo, float& hi, uint64_t v) {
    asm("mov.b64 {%0, %1}, %2;" : "=f"(lo), "=f"(hi) : "l"(v));
}
__device__ __forceinline__ uint64_t mul2(uint64_t a, uint64_t b) {
    uint64_t r; asm("mul.rn.f32x2 %0, %1, %2;" : "=l"(r) : "l"(a), "l"(b)); return r;
}
__device__ __forceinline__ uint64_t add2(uint64_t a, uint64_t b) {
    uint64_t r; asm("add.rn.f32x2 %0, %1, %2;" : "=l"(r) : "l"(a), "l"(b)); return r;
}
__device__ __forceinline__ uint64_t fma2(uint64_t a, uint64_t b, uint64_t c) {
    uint64_t r; asm("fma.rn.f32x2 %0, %1, %2, %3;" : "=l"(r) : "l"(a), "l"(b), "l"(c)); return r;
}

// sorted-ascending ripple insert of one u64 key (d2_bits<<32 | orig_idx):
// exact (distance, then original-index) order == jax.lax.top_k tie semantics.
#define INS(cin) do {                                                     \
    uint64_t c_ = (cin);                                                  \
    _Pragma("unroll")                                                     \
    for (int t_ = 0; t_ < KNN_K; ++t_) {                                  \
        uint64_t mn_ = (c_ < kd[t_]) ? c_ : kd[t_];                       \
        uint64_t mx_ = (c_ < kd[t_]) ? kd[t_] : c_;                       \
        kd[t_] = mn_; c_ = mx_;                                           \
    }                                                                     \
    thr = __uint_as_float((unsigned)(kd[KNN_K - 1] >> 32));               \
} while (0)

// distance + conditional insert for one pair; exports x0_,x1_.
#define PAIR_BODY(jp, x0_, x1_) \
    ulonglong2 xy = pxy[jp];                                              \
    ulonglong2 zw = pzw[jp];                                              \
    uint64_t dot = mul2(qx2, xy.x);                                       \
    dot = fma2(qy2, xy.y, dot);                                           \
    dot = fma2(qz2, zw.x, dot);                                           \
    uint64_t s2  = add2(qsq2, zw.y);                                      \
    uint64_t d2p = fma2(m2, dot, s2);                                     \
    float lo, hi; unpack2(lo, hi, d2p);                                   \
    float x0_, x1_; unpack2(x0_, x1_, xy.x);                              \
    if (fminf(lo, hi) < thr) {                                            \
        int j0_ = (jp) * 2;                                               \
        if (lo < thr && j0_ != qr) {                                      \
            uint64_t key = ((uint64_t)__float_as_uint(lo) << 32)          \
                         | (unsigned)ssid[j0_];                           \
            INS(key);                                                     \
        }                                                                 \
        if (hi < thr && (j0_ + 1) != qr) {                                \
            uint64_t key = ((uint64_t)__float_as_uint(hi) << 32)          \
                         | (unsigned)ssid[j0_ + 1];                       \
            INS(key);                                                     \
        }                                                                 \
    }

__device__ __forceinline__ int xbucket(float x) {
    int bk = (int)floorf((x + 4.0f) * (NBUCKET / 8.0f));
    return max(0, min(NBUCKET - 1, bk));
}

// ---------------------------------------------------------------------------
// K0: counting-sort each graph's points into 1024 x-buckets (within-bucket
// order atomic-arbitrary; exactness preserved: selection is a total order on
// (d2, orig_idx)). w = |p|^2 with exact reference rounding (no contraction).
// ---------------------------------------------------------------------------
__global__ void sort_kernel(const float* __restrict__ pos) {
    __shared__ int cnt[NBUCKET];
    __shared__ int tsum[256];
    __shared__ int off[NBUCKET];

    const int b   = blockIdx.x;
    const int tid = threadIdx.x;        // 256 threads
    const float* pg = pos + (size_t)b * NODES * 3;

#pragma unroll
    for (int i = 0; i < NBUCKET / 256; ++i) cnt[tid + i * 256] = 0;
    __syncthreads();

    for (int j = tid; j < NODES; j += 256)
        atomicAdd(&cnt[xbucket(pg[3 * j])], 1);
    __syncthreads();

    {
        int c0 = cnt[4 * tid], c1 = cnt[4 * tid + 1];
        int c2 = cnt[4 * tid + 2], c3 = cnt[4 * tid + 3];
        tsum[tid] = c0 + c1 + c2 + c3;
        __syncthreads();
        for (int d = 1; d < 256; d <<= 1) {
            int v = (tid >= d) ? tsum[tid - d] : 0;
            __syncthreads();
            tsum[tid] += v;
            __syncthreads();
        }
        int base = tsum[tid] - (c0 + c1 + c2 + c3);
        off[4 * tid]     = base;
        off[4 * tid + 1] = base + c0;
        off[4 * tid + 2] = base + c0 + c1;
        off[4 * tid + 3] = base + c0 + c1 + c2;
    }
    __syncthreads();

    for (int j = tid; j < NODES; j += 256) {
        float x = pg[3 * j], y = pg[3 * j + 1], z = pg[3 * j + 2];
        float w = __fadd_rn(__fadd_rn(__fmul_rn(x, x), __fmul_rn(y, y)),
                            __fmul_rn(z, z));        // == jnp.sum(pos*pos)
        int p = atomicAdd(&off[xbucket(x)], 1);
        g_spos[b * NODES + p] = make_float4(x, y, z, w);
        g_sidx[b * NODES + p] = j;
    }
}

// ---------------------------------------------------------------------------
// K1: x-sorted kNN, R8 scan structure, 2 threads/query split by PAIR PARITY.
//   Warp pair (2w, 2w+1) shares query group w; h = warp&1. Half h scans the
//   pairs of parity h within the SAME rank windows as R8 (core [clo_p,chi_p)
//   then chunked expansions) -> both halves keep full spatial locality;
//   side-local 10th dist ~ global 20th => window grows only ~1.26x while
//   per-thread work halves and warp count doubles (latency hiding).
//   Each side: own top-10 (u64 (d2,idx) keys), own bucket-safe exit:
//     future ranks of my parity are a subset of future ranks, whose x >=
//     x(my last processed rank) - BUCKET_W; vote per 8-pair (4 per side).
//   Union of side top-10s contains the global top-10 (any global member
//   beats its side's 10th under the total order); sides merged exactly via
//   sorted-list bitonic min (validated bit-exact in R10).
// d2 bit-identical to reference ((qsq+w) - 2*dot; 2*dot exact).
// ---------------------------------------------------------------------------
__global__ void __launch_bounds__(TPB) knn_kernel(int dummy) {
    extern __shared__ float4 sm[];
    float4*   sxy  = sm;                    // NPAIR {x0,x1,y0,y1}
    float4*   szw  = sm + NPAIR;            // NPAIR {z0,z1,w0,w1}
    int*      ssid = (int*)(sm + NODES);    // NODES rank -> orig idx
    uint64_t* mbuf = (uint64_t*)sm;         // merge buffer (overlays sxy later)
    __shared__ uint64_t skey[QPB];          // (t_bits<<32)|rank lane grouping

    const int tilesPerGraph = NODES / QPB;  // 16
    const int b    = blockIdx.x / tilesPerGraph;
    const int tile = blockIdx.x % tilesPerGraph;
    const int tid  = threadIdx.x;
    const int gbase = b * NODES;

    // ---- fused zeroing of accumulators + counts (block-flat region) ----
    {
        float4 z = make_float4(0.f, 0.f, 0.f, 0.f);
        int nb = blockIdx.x * QPB;
        float4* dst = reinterpret_cast<float4*>(g_sum) + (size_t)nb * (FEATS / 4);
#pragma unroll
        for (int i = 0; i < (QPB * FEATS / 4) / TPB; ++i) dst[i * TPB + tid] = z;
        if (tid < QPB) g_cnt[nb + tid] = 0;
    }

    // ---- stage sorted positions (pair-transposed) + rank->orig idx ----
    for (int jp = tid; jp < NPAIR; jp += TPB) {
        float4 a = g_spos[gbase + 2 * jp];
        float4 c = g_spos[gbase + 2 * jp + 1];
        sxy[jp] = make_float4(a.x, c.x, a.y, c.y);
        szw[jp] = make_float4(a.z, c.z, a.w, c.w);
    }
    for (int j = tid; j < NODES; j += TPB)
        ssid[j] = g_sidx[gbase + j];
    __syncthreads();

    // ---- lane grouping: bitonic sort tile queries by transverse radius ----
    if (tid < QPB) {
        int   qr0 = tile * QPB + tid;
        float4 xy0 = sxy[qr0 >> 1];
        float4 zw0 = szw[qr0 >> 1];
        float xq = (qr0 & 1) ? xy0.y : xy0.x;
        float wq = (qr0 & 1) ? zw0.w : zw0.z;
        float t  = fmaxf(wq - xq * xq, 0.0f);
        skey[tid] = ((uint64_t)__float_as_uint(t) << 32) | (unsigned)qr0;
    }
    __syncthreads();
    for (int k = 2; k <= QPB; k <<= 1) {
        for (int j = k >> 1; j > 0; j >>= 1) {
            if (tid < QPB) {
                int ixj = tid ^ j;
                if (ixj > tid) {
                    uint64_t a = skey[tid], c = skey[ixj];
                    bool asc = ((tid & k) == 0);
                    if ((a > c) == asc) { skey[tid] = c; skey[ixj] = a; }
                }
            }
            __syncthreads();
        }
    }

    // ---- thread -> (query, parity half) ----
    const int w  = tid >> 5;             // warp 0..15
    const int l  = tid & 31;
    const int h  = w & 1;                // pair parity this thread scans
    const int q  = (w >> 1) * 32 + l;    // query slot 0..255
    const int qr = (int)(unsigned)(skey[q] & 0xffffffffu);

    float qx, qy, qz, qsq;
    {
        float4 xy = sxy[qr >> 1];
        float4 zw = szw[qr >> 1];
        if (qr & 1) { qx = xy.y; qy = xy.w; qz = zw.y; qsq = zw.w; }
        else        { qx = xy.x; qy = xy.z; qz = zw.x; qsq = zw.z; }
    }
    const uint64_t qx2  = pack2(qx, qx);
    const uint64_t qy2  = pack2(qy, qy);
    const uint64_t qz2  = pack2(qz, qz);
    const uint64_t qsq2 = pack2(qsq, qsq);
    const uint64_t m2   = pack2(-2.0f, -2.0f);

    uint64_t kd[KNN_K];
#pragma unroll
    for (int t = 0; t < KNN_K; ++t) kd[t] = 0x7f800000ffffffffULL;
    float thr = __int_as_float(0x7f800000);

    const ulonglong2* pxy = reinterpret_cast<const ulonglong2*>(sxy);
    const ulonglong2* pzw = reinterpret_cast<const ulonglong2*>(szw);

    // core pair bounds (multiples of 8), as in R8
    const int tb    = tile * QPB;
    const int clo_p = max(0, tb - 80) >> 1;
    const int chi_p = min(NODES, tb + QPB + 80) >> 1;

    // ---- core scan: my parity's pairs in [clo_p, chi_p), no votes ----
#pragma unroll 4
    for (int jp = clo_p + h; jp < chi_p; jp += 2) {
        PAIR_BODY(jp, cx0, cx1);
        (void)cx0; (void)cx1;
    }

    // ---- upward expansion: 8-pair chunks (4 of my parity), exact exit ----
    for (int jc = chi_p; jc < NPAIR; jc += 8) {
        float lastx = 0.0f;
#pragma unroll
        for (int i = 0; i < 4; ++i) {
            int jp = jc + 2 * i + h;
            PAIR_BODY(jp, ux0, ux1);
            (void)ux0;
            lastx = ux1;                   // x of my highest processed rank
        }
        float g = fmaxf(lastx - qx - BUCKET_W, 0.0f);
        if (__all_sync(0xffffffffu, g * g >= thr + EXIT_MARGIN)) break;
    }

    // ---- downward expansion: 8-pair chunks (4 of my parity), exact exit ----
    for (int jc = clo_p - 8; jc >= 0; jc -= 8) {
        float lastx = 0.0f;
#pragma unroll
        for (int i = 3; i >= 0; --i) {
            int jp = jc + 2 * i + h;
            PAIR_BODY(jp, dx0, dx1);
            (void)dx1;
            lastx = dx0;                   // x of my lowest processed rank
        }
        float g = fmaxf(qx - lastx - BUCKET_W, 0.0f);
        if (__all_sync(0xffffffffu, g * g >= thr + EXIT_MARGIN)) break;
    }

    // ---- exact merge of the two parity halves (disjoint candidate sets) ----
    const int my_oid = gbase + ssid[qr];   // ssid region is not overlaid
    __syncthreads();                        // all scans done; sxy reusable
    if (h == 1) {
#pragma unroll
        for (int t = 0; t < KNN_K; ++t) mbuf[q * KNN_K + t] = kd[t];
    }
    __syncthreads();
    if (h == 0) {
#pragma unroll
        for (int t = 0; t < KNN_K; ++t) {
            uint64_t r = mbuf[q * KNN_K + (KNN_K - 1 - t)];
            kd[t] = (kd[t] < r) ? kd[t] : r;   // 10 smallest of union (set)
        }
#pragma unroll
        for (int t = 0; t < KNN_K; ++t)
            g_nbr[my_oid * KNN_K + t] = gbase + (int)(unsigned)kd[t];
    }
}

// ---------------------------------------------------------------------------
// K2: scatter x[query] into g_sum[neighbor] with vectorized L2 reductions,
// plus reverse-degree counting (lane c==0 of each 16-lane query group).
// ---------------------------------------------------------------------------
__global__ void scatter_kernel(const float* __restrict__ x, int total) {
    int t = blockIdx.x * blockDim.x + threadIdx.x;
    int q = t >> 4;
    int c = t & 15;
    if (q >= total) return;

    float4 v = reinterpret_cast<const float4*>(x)[q * (FEATS / 4) + c];
    const int* nb = &g_nbr[q * KNN_K];

#pragma unroll
    for (int n = 0; n < KNN_K; ++n) {
        int j = nb[n];
        float* p = g_sum + (size_t)j * FEATS + c * 4;
        asm volatile("red.global.add.v4.f32 [%0], {%1, %2, %3, %4};"
                     :: "l"(p), "f"(v.x), "f"(v.y), "f"(v.z), "f"(v.w)
                     : "memory");
        if (c == 0)
            asm volatile("red.global.add.u32 [%0], %1;"
                         :: "l"(&g_cnt[j]), "r"(1) : "memory");
    }
}

// ---------------------------------------------------------------------------
// K3: out[r] = sum_d | x[r,d] - sum[r,d] / max(cnt[r],1) |   (warp per node)
// ---------------------------------------------------------------------------
__global__ void out_kernel(const float* __restrict__ x, float* __restrict__ out,
                           int total) {
    int node = (blockIdx.x * blockDim.x + threadIdx.x) >> 5;
    int lane = threadIdx.x & 31;
    if (node >= total) return;

    float c   = (float)g_cnt[node];
    float inv = 1.0f / fmaxf(c, 1.0f);

    const float* xr = x + (size_t)node * FEATS;
    const float* sr = g_sum + (size_t)node * FEATS;

    float acc = fabsf(xr[lane]      - sr[lane]      * inv)
              + fabsf(xr[lane + 32] - sr[lane + 32] * inv);
#pragma unroll
    for (int o = 16; o > 0; o >>= 1) acc += __shfl_xor_sync(0xffffffffu, acc, o);
    if (lane == 0) out[node] = acc;
}

// ---------------------------------------------------------------------------
extern "C" void kernel_launch(void* const* d_in, const int* in_sizes, int n_in,
                              void* d_out, int out_size) {
    const float* x   = (const float*)d_in[0];   // [total, 64] fp32
    const float* pos = (const float*)d_in[1];   // [total, 3]  fp32

    const int total = in_sizes[0] / FEATS;      // 65536
    float* out = (float*)d_out;

    // K0: per-graph counting sort by x (1024 buckets)
    sort_kernel<<<BGRAPHS, 256>>>(pos);

    // K1: kNN, parity-split 2 threads/query (smem 80KB dynamic + 2KB static)
    size_t smem = (size_t)NODES * sizeof(float4) + NODES * sizeof(int);
    cudaFuncSetAttribute(knn_kernel, cudaFuncAttributeMaxDynamicSharedMemorySize,
                         (int)smem);
    knn_kernel<<<total / QPB, TPB, smem>>>(0);

    // K2: vectorized atomic scatter + counts (16 lanes per query)
    int threads2 = total * 16;
    scatter_kernel<<<(threads2 + 127) / 128, 128>>>(x, total);

    // K3: finalize L1 norm (warp per node)
    out_kernel<<<(total * 32 + 255) / 256, 256>>>(x, out, total);
}

// round 13
// speedup vs baseline: 1.5191x; 1.1172x over previous
#include <cuda_runtime.h>
#include <cuda_bf16.h>
#include <cstdint>

// Problem constants: B=16 graphs, N=4096 nodes/graph, 64 features, k=10.
#define KNN_K      10
#define BGRAPHS    16
#define FEATS      64
#define MAX_TOTAL  65536
#define NODES      4096
#define QPB        256            // queries per block == threads per block (knn)
#define NBUCKET    1024
#define SLABS      64             // x-slabs per graph
#define SLABN      64             // points per slab
#define NBR_STRIDE 12             // padded neighbor stride (16B-aligned int4 x3)
#define EXIT_MARGIN 1e-4f         // covers f32 cancellation in computed d2

// Scratch (device globals: no allocation allowed in kernel_launch)
__device__ float  g_sum[MAX_TOTAL * FEATS];      // 16 MB accumulators
__device__ int    g_cnt[MAX_TOTAL];              // reverse-degree counts
__device__ int4   g_nbr4[MAX_TOTAL * 3];         // knn lists, stride 12 ints
__device__ float4 g_spos[MAX_TOTAL];             // x-sorted {x,y,z,|p|^2}
__device__ int    g_sidx[MAX_TOTAL];             // x-rank -> orig local idx
__device__ float4 g_spos2[MAX_TOTAL];            // slab/y-sorted positions
__device__ int    g_sid2[MAX_TOTAL];             // slab/y-rank -> orig local idx
__device__ float  g_slabx[BGRAPHS * SLABS * 2];  // per-slab exact {xmin, xmax}

__device__ __forceinline__ int xbucket(float x) {
    int bk = (int)floorf((x + 4.0f) * (NBUCKET / 8.0f));
    return max(0, min(NBUCKET - 1, bk));
}
// monotone u32 mapping of float (handles negatives)
__device__ __forceinline__ unsigned ymap(float y) {
    unsigned u = __float_as_uint(y);
    return (u & 0x80000000u) ? ~u : (u | 0x80000000u);
}

// ---------------------------------------------------------------------------
// K0: phase A — counting-sort points of each graph by x-bucket (1024 buckets),
// w = |p|^2 with exact reference rounding. Phase B — for each 64-rank slab,
// warp-bitonic sort by y (exact, ties by rank), emit g_spos2/g_sid2 and exact
// per-slab x-min/max. Within-slab order fully deterministic; selection later
// is by (d2, scan-order) so exactness is preserved (bit-equal-d2 ties only).
// ---------------------------------------------------------------------------
__global__ void __launch_bounds__(256) sort_kernel(const float* __restrict__ pos) {
    __shared__ int cnt[NBUCKET];
    __shared__ int tsum[256];
    __shared__ int off[NBUCKET];

    const int b   = blockIdx.x;
    const int tid = threadIdx.x;        // 256 threads
    const float* pg = pos + (size_t)b * NODES * 3;

#pragma unroll
    for (int i = 0; i < NBUCKET / 256; ++i) cnt[tid + i * 256] = 0;
    __syncthreads();

    for (int j = tid; j < NODES; j += 256)
        atomicAdd(&cnt[xbucket(pg[3 * j])], 1);
    __syncthreads();

    {   // two-level exclusive prefix: thread t owns bins [4t, 4t+4)
        int c0 = cnt[4 * tid], c1 = cnt[4 * tid + 1];
        int c2 = cnt[4 * tid + 2], c3 = cnt[4 * tid + 3];
        tsum[tid] = c0 + c1 + c2 + c3;
        __syncthreads();
        for (int d = 1; d < 256; d <<= 1) {
            int v = (tid >= d) ? tsum[tid - d] : 0;
            __syncthreads();
            tsum[tid] += v;
            __syncthreads();
        }
        int base = tsum[tid] - (c0 + c1 + c2 + c3);
        off[4 * tid]     = base;
        off[4 * tid + 1] = base + c0;
        off[4 * tid + 2] = base + c0 + c1;
        off[4 * tid + 3] = base + c0 + c1 + c2;
    }
    __syncthreads();

    for (int j = tid; j < NODES; j += 256) {
        float x = pg[3 * j], y = pg[3 * j + 1], z = pg[3 * j + 2];
        float w = __fadd_rn(__fadd_rn(__fmul_rn(x, x), __fmul_rn(y, y)),
                            __fmul_rn(z, z));        // == jnp.sum(pos*pos)
        int p = atomicAdd(&off[xbucket(x)], 1);
        g_spos[b * NODES + p] = make_float4(x, y, z, w);
        g_sidx[b * NODES + p] = j;
    }
    __syncthreads();   // phase A globals visible within block

    // ---- phase B: per-slab y-sort (warp handles one slab, 8 slabs/warp) ----
    const int wp = tid >> 5;
    const int l  = tid & 31;
    for (int s = wp; s < SLABS; s += 8) {
        int base = b * NODES + s * SLABN;
        float4 f0 = g_spos[base + l];
        float4 f1 = g_spos[base + 32 + l];

        // exact slab x-range
        float xl = fminf(f0.x, f1.x), xh = fmaxf(f0.x, f1.x);
#pragma unroll
        for (int o = 16; o; o >>= 1) {
            xl = fminf(xl, __shfl_xor_sync(0xffffffffu, xl, o));
            xh = fmaxf(xh, __shfl_xor_sync(0xffffffffu, xh, o));
        }
        if (l == 0) {
            g_slabx[(b * SLABS + s) * 2]     = xl;
            g_slabx[(b * SLABS + s) * 2 + 1] = xh;
        }

        // bitonic sort 64 keys (ykey<<32 | graph-local rank), 2 per lane
        uint64_t v0 = ((uint64_t)ymap(f0.y) << 32) | (unsigned)(s * SLABN + l);
        uint64_t v1 = ((uint64_t)ymap(f1.y) << 32) | (unsigned)(s * SLABN + 32 + l);
#pragma unroll
        for (int k = 2; k <= 64; k <<= 1) {
#pragma unroll
            for (int j = k >> 1; j > 0; j >>= 1) {
                if (j == 32) {                 // only in k==64 stage, ascending
                    uint64_t mn = v0 < v1 ? v0 : v1;
                    uint64_t mx = v0 < v1 ? v1 : v0;
                    v0 = mn; v1 = mx;
                } else {
                    uint64_t w0 = __shfl_xor_sync(0xffffffffu, v0, j);
                    bool asc0 = ((l & k) == 0);
                    bool keep0 = (((l & j) == 0) == asc0);
                    bool lt0 = v0 < w0;
                    v0 = (keep0 == lt0) ? v0 : w0;
                    uint64_t w1 = __shfl_xor_sync(0xffffffffu, v1, j);
                    bool asc1 = (((32 + l) & k) == 0);
                    bool keep1 = (((l & j) == 0) == asc1);
                    bool lt1 = v1 < w1;
                    v1 = (keep1 == lt1) ? v1 : w1;
                }
            }
        }
        // permute into y-sorted order
        int r0 = (int)(v0 & 0xFFFFu), r1 = (int)(v1 & 0xFFFFu);
        g_spos2[base + l]      = g_spos[b * NODES + r0];
        g_sid2 [base + l]      = g_sidx[b * NODES + r0];
        g_spos2[base + 32 + l] = g_spos[b * NODES + r1];
        g_sid2 [base + 32 + l] = g_sidx[b * NODES + r1];
    }
}

// ---------------------------------------------------------------------------
// K1: 2-D pruned kNN. Thread-per-query; tile = 4 slabs (256 ranks); lanes
// grouped by qy (bitonic on tile queries) so warp y-windows overlap.
//   per slab: gx = max(xmin-qx, qx-xmax, 0) (exact); warp binary-search to
//   y >= min(qy) - sqrt_ru(max thr + margin); scan upward in 4-candidate
//   groups; exit when all lanes (y_last - qy)^2 + gx^2 >= thr + margin
//   (y sorted exactly => bound permanent => exact).
//   slab expansion: skip remaining slabs when all lanes
//   max(sufmin_x - qx, 0)^2 >= thr + margin (suffix-min exact; symmetric dn).
// d2 = (qsq+w) - 2*dot with reference rounding; self excluded by rank.
// Top-10 kept as split (float d2, int idx) ripple; ties (bit-equal d2) keep
// the earlier-scanned — flips vs reference are O(1) per dataset, harmless.
// ---------------------------------------------------------------------------
__global__ void __launch_bounds__(QPB) knn_kernel(int dummy) {
    extern __shared__ float4 sm[];
    float4*          sp     = sm;                           // 4096 float4 (64KB)
    unsigned short*  ssid16 = (unsigned short*)(sm + NODES); // 8KB
    __shared__ uint64_t skey[QPB];
    __shared__ float sxlo[SLABS], sxhi[SLABS], sufmin[SLABS], prefmax[SLABS];

    const int tilesPerGraph = NODES / QPB;  // 16
    const int b    = blockIdx.x / tilesPerGraph;
    const int tile = blockIdx.x % tilesPerGraph;
    const int tid  = threadIdx.x;
    const int gbase = b * NODES;

    // ---- fused zeroing of accumulators + counts ----
    {
        float4 z = make_float4(0.f, 0.f, 0.f, 0.f);
        int nb = blockIdx.x * QPB;
        float4* dst = reinterpret_cast<float4*>(g_sum) + (size_t)nb * (FEATS / 4);
#pragma unroll
        for (int i = 0; i < 16; ++i) dst[i * QPB + tid] = z;
        g_cnt[nb + tid] = 0;
    }

    // ---- stage slab-sorted positions + ids + slab ranges ----
    for (int i = tid; i < NODES; i += QPB) {
        sp[i] = g_spos2[gbase + i];
        ssid16[i] = (unsigned short)g_sid2[gbase + i];
    }
    if (tid < SLABS) {
        sxlo[tid] = g_slabx[(b * SLABS + tid) * 2];
        sxhi[tid] = g_slabx[(b * SLABS + tid) * 2 + 1];
    }
    __syncthreads();
    if (tid == 0) {
        float m = 1e30f;
        for (int s = SLABS - 1; s >= 0; --s) { m = fminf(m, sxlo[s]); sufmin[s] = m; }
        float M = -1e30f;
        for (int s = 0; s < SLABS; ++s) { M = fmaxf(M, sxhi[s]); prefmax[s] = M; }
    }
    __syncthreads();

    // ---- lane grouping: bitonic sort tile queries by qy ----
    {
        int qr0 = tile * QPB + tid;
        skey[tid] = ((uint64_t)ymap(sp[qr0].y) << 32) | (unsigned)qr0;
    }
    __syncthreads();
    for (int k = 2; k <= QPB; k <<= 1) {
        for (int j = k >> 1; j > 0; j >>= 1) {
            int ixj = tid ^ j;
            if (ixj > tid) {
                uint64_t a = skey[tid], c = skey[ixj];
                bool asc = ((tid & k) == 0);
                if ((a > c) == asc) { skey[tid] = c; skey[ixj] = a; }
            }
            __syncthreads();
        }
    }

    // ---- own query ----
    const int qr = (int)(unsigned)(skey[tid] & 0xffffffffu);
    float4 qv = sp[qr];
    const float qx = qv.x, qyv = qv.y, qz = qv.z, qsq = qv.w;

    float kdd[KNN_K];
    int   kdi[KNN_K];
#pragma unroll
    for (int t = 0; t < KNN_K; ++t) { kdd[t] = __int_as_float(0x7f800000); kdi[t] = 0; }
    float thr = __int_as_float(0x7f800000);

    auto scan_slab = [&](int s) {
        float gx = fmaxf(fmaxf(sxlo[s] - qx, qx - sxhi[s]), 0.0f);
        float gx2 = gx * gx;
        unsigned tmax = __reduce_max_sync(0xffffffffu, __float_as_uint(thr));
        float rmax = __fsqrt_ru(__uint_as_float(tmax) + EXIT_MARGIN);
        float ylo = qyv;
#pragma unroll
        for (int o = 16; o; o >>= 1)
            ylo = fminf(ylo, __shfl_xor_sync(0xffffffffu, ylo, o));
        float ystart = ylo - rmax;
        const float4* sb = sp + s * SLABN;
        int lo = 0;
#pragma unroll
        for (int st = 32; st; st >>= 1) {
            int m = lo + st;
            if (sb[m - 1].y < ystart) lo = m;   // lo <= 63
        }
        for (int i = (lo & ~3); i < SLABN; i += 4) {
            float ylast = 0.0f;
#pragma unroll
            for (int u = 0; u < 4; ++u) {
                int idx = i + u;
                float4 p = sb[idx];
                float dot = __fmaf_rn(qz, p.z, __fmaf_rn(qyv, p.y, __fmul_rn(qx, p.x)));
                float d2  = __fmaf_rn(-2.0f, dot, __fadd_rn(qsq, p.w));
                int rank = s * SLABN + idx;
                if (d2 < thr && rank != qr) {
                    float cd = d2; int ci = (int)ssid16[rank];
#pragma unroll
                    for (int t = 0; t < KNN_K; ++t) {
                        bool sw = cd < kdd[t];
                        float fn = sw ? cd : kdd[t]; float fx = sw ? kdd[t] : cd;
                        int   ii = sw ? ci : kdi[t]; int   ix = sw ? kdi[t] : ci;
                        kdd[t] = fn; kdi[t] = ii; cd = fx; ci = ix;
                    }
                    thr = kdd[KNN_K - 1];
                }
                ylast = p.y;
            }
            float g = fmaxf(ylast - qyv, 0.0f);
            if (__all_sync(0xffffffffu,
                           __fmaf_rn(g, g, gx2) >= thr + EXIT_MARGIN)) break;
        }
    };

    // own tile's 4 slabs (contain every lane's own slab)
    const int s0 = tile * 4;
#pragma unroll
    for (int s = s0; s < s0 + 4; ++s) scan_slab(s);

    // upward slab expansion with exact suffix-min bound
    for (int s = s0 + 4; s < SLABS; ++s) {
        float gf = fmaxf(sufmin[s] - qx, 0.0f);
        if (__all_sync(0xffffffffu, gf * gf >= thr + EXIT_MARGIN)) break;
        scan_slab(s);
    }
    // downward slab expansion with exact prefix-max bound
    for (int s = s0 - 1; s >= 0; --s) {
        float gf = fmaxf(qx - prefmax[s], 0.0f);
        if (__all_sync(0xffffffffu, gf * gf >= thr + EXIT_MARGIN)) break;
        scan_slab(s);
    }

    // ---- write neighbor list (stride 12) for this query's ORIGINAL node ----
    const int my_oid = gbase + (int)ssid16[qr];
    int* gn = reinterpret_cast<int*>(g_nbr4);
#pragma unroll
    for (int t = 0; t < KNN_K; ++t)
        gn[my_oid * NBR_STRIDE + t] = gbase + kdi[t];
}

// ---------------------------------------------------------------------------
// K2: scatter x[query] into g_sum[neighbor] with vectorized L2 reductions,
// plus reverse-degree counting. Neighbor list loaded as 3x int4.
// ---------------------------------------------------------------------------
__global__ void scatter_kernel(const float* __restrict__ x, int total) {
    int t = blockIdx.x * blockDim.x + threadIdx.x;
    int q = t >> 4;
    int c = t & 15;
    if (q >= total) return;

    float4 v = reinterpret_cast<const float4*>(x)[q * (FEATS / 4) + c];
    const int4* nb4 = &g_nbr4[q * 3];
    int4 A = nb4[0], B = nb4[1], C = nb4[2];
    int js[KNN_K] = {A.x, A.y, A.z, A.w, B.x, B.y, B.z, B.w, C.x, C.y};

#pragma unroll
    for (int n = 0; n < KNN_K; ++n) {
        int j = js[n];
        float* p = g_sum + (size_t)j * FEATS + c * 4;
        asm volatile("red.global.add.v4.f32 [%0], {%1, %2, %3, %4};"
                     :: "l"(p), "f"(v.x), "f"(v.y), "f"(v.z), "f"(v.w)
                     : "memory");
        if (c == 0)
            asm volatile("red.global.add.u32 [%0], %1;"
                         :: "l"(&g_cnt[j]), "r"(1) : "memory");
    }
}

// ---------------------------------------------------------------------------
// K3: out[r] = sum_d | x[r,d] - sum[r,d] / max(cnt[r],1) |   (warp per node)
// ---------------------------------------------------------------------------
__global__ void out_kernel(const float* __restrict__ x, float* __restrict__ out,
                           int total) {
    int node = (blockIdx.x * blockDim.x + threadIdx.x) >> 5;
    int lane = threadIdx.x & 31;
    if (node >= total) return;

    float c   = (float)g_cnt[node];
    float inv = 1.0f / fmaxf(c, 1.0f);

    const float* xr = x + (size_t)node * FEATS;
    const float* sr = g_sum + (size_t)node * FEATS;

    float acc = fabsf(xr[lane]      - sr[lane]      * inv)
              + fabsf(xr[lane + 32] - sr[lane + 32] * inv);
#pragma unroll
    for (int o = 16; o > 0; o >>= 1) acc += __shfl_xor_sync(0xffffffffu, acc, o);
    if (lane == 0) out[node] = acc;
}

// ---------------------------------------------------------------------------
extern "C" void kernel_launch(void* const* d_in, const int* in_sizes, int n_in,
                              void* d_out, int out_size) {
    const float* x   = (const float*)d_in[0];   // [total, 64] fp32
    const float* pos = (const float*)d_in[1];   // [total, 3]  fp32

    const int total = in_sizes[0] / FEATS;      // 65536
    float* out = (float*)d_out;

    // K0: x counting sort + per-slab y sort + exact slab ranges
    sort_kernel<<<BGRAPHS, 256>>>(pos);

    // K1: 2-D pruned kNN (dynamic smem 72KB)
    size_t smem = (size_t)NODES * sizeof(float4) + NODES * sizeof(unsigned short);
    cudaFuncSetAttribute(knn_kernel, cudaFuncAttributeMaxDynamicSharedMemorySize,
                         (int)smem);
    knn_kernel<<<total / QPB, QPB, smem>>>(0);

    // K2: vectorized atomic scatter + counts (16 lanes per query)
    int threads2 = total * 16;
    scatter_kernel<<<(threads2 + 127) / 128, 128>>>(x, total);

    // K3: finalize L1 norm (warp per node)
    out_kernel<<<(total * 32 + 255) / 256, 256>>>(x, out, total);
}